// round 4
// baseline (speedup 1.0000x reference)
#include <cuda_runtime.h>
#include <cuda_fp16.h>
#include <cstdint>

#define BATCH  32768
#define DIM    128
#define HID    256
#define NSTEPS 50
#define TILE_M 128
#define NTILES (BATCH / TILE_M)   // 256

// ---------------- SMEM layout (bytes) ----------------
// dts[64] f32 | b1[256] f32 | b2[128] f32 | W1^T f16 [256][136] | W2^T f16 [128][264]
#define SMEM_DTS   0
#define SMEM_B1S   256
#define SMEM_B2S   1280
#define SMEM_W1T   2048
#define W1T_STRIDE 136                      // f16 elems/row = 272 B (17*16B, conflict-free, 16B aligned)
#define SMEM_W2T   (SMEM_W1T + 256 * 272)   // 71680
#define W2T_STRIDE 264                      // 528 B (33*16B)
#define SMEM_BYTES (SMEM_W2T + 128 * 528)   // 139264

__device__ __forceinline__ uint32_t smem_u32(const void* p) {
    uint32_t a;
    asm("{ .reg .u64 t; cvta.to.shared.u64 t, %1; cvt.u32.u64 %0, t; }" : "=r"(a) : "l"(p));
    return a;
}

// pack two f32 -> f16x2 (lo = first arg)
__device__ __forceinline__ uint32_t pack2(float lo, float hi) {
    uint32_t r;
    asm("cvt.rn.f16x2.f32 %0, %1, %2;" : "=r"(r) : "f"(hi), "f"(lo));
    return r;
}

__device__ __forceinline__ void ldsm4(uint32_t& r0, uint32_t& r1, uint32_t& r2, uint32_t& r3, uint32_t addr) {
    asm volatile("ldmatrix.sync.aligned.m8n8.x4.shared.b16 {%0,%1,%2,%3}, [%4];"
        : "=r"(r0), "=r"(r1), "=r"(r2), "=r"(r3) : "r"(addr));
}

__device__ __forceinline__ void mma16816(float* c, uint32_t a0, uint32_t a1, uint32_t a2, uint32_t a3,
                                         uint32_t b0, uint32_t b1) {
    asm volatile("mma.sync.aligned.m16n8k16.row.col.f32.f16.f16.f32 "
        "{%0,%1,%2,%3},{%4,%5,%6,%7},{%8,%9},{%0,%1,%2,%3};"
        : "+f"(c[0]), "+f"(c[1]), "+f"(c[2]), "+f"(c[3])
        : "r"(a0), "r"(a1), "r"(a2), "r"(a3), "r"(b0), "r"(b1));
}

__device__ __forceinline__ float tanh_approx(float x) {
    float y;
    asm("tanh.approx.f32 %0, %1;" : "=f"(y) : "f"(x));
    return y;
}

__global__ void __launch_bounds__(256, 1) ode_kernel(
    const float* __restrict__ inp, const float* __restrict__ ts,
    const float* __restrict__ W1, const float* __restrict__ b1,
    const float* __restrict__ W2, const float* __restrict__ b2,
    float* __restrict__ out)
{
    extern __shared__ char smem[];
    const uint32_t sb = smem_u32(smem);
    const int tid  = threadIdx.x;
    const int lane = tid & 31;
    const int wid  = tid >> 5;          // 8 warps, each owns 16 rows
    const int g    = lane >> 2;         // group id 0..7
    const int tg   = lane & 3;          // thread-in-group

    // ---- stage constants ----
    if (tid < NSTEPS) ((float*)(smem + SMEM_DTS))[tid] = ts[tid + 1] - ts[tid];
    for (int i = tid; i < HID; i += 256) ((float*)(smem + SMEM_B1S))[i] = b1[i];
    for (int i = tid; i < DIM; i += 256) ((float*)(smem + SMEM_B2S))[i] = b2[i];

    // ---- weights -> SMEM f16, transposed, padded strides ----
    __half* W1t = (__half*)(smem + SMEM_W1T);   // [n=256][k padded 136]
    __half* W2t = (__half*)(smem + SMEM_W2T);   // [n=128][k padded 264]
    for (int idx = tid; idx < DIM * HID; idx += 256) {      // W1: [128 k][256 n] row-major
        int n = idx & 255, k = idx >> 8;                    // gmem-coalesced over n
        W1t[n * W1T_STRIDE + k] = __float2half_rn(W1[k * HID + n]);
    }
    for (int idx = tid; idx < DIM * HID; idx += 256) {      // W2: [256 k][128 n]
        int n = idx & 127, k = idx >> 7;
        W2t[n * W2T_STRIDE + k] = __float2half_rn(W2[k * DIM + n]);
    }
    __syncthreads();

    // ---- ldmatrix per-lane address components ----
    // x4 layout: q=lane>>3 selects matrix: q0:(n+0..7,k lo8) q1:(n,k hi8) q2:(n+8,k lo) q3:(n+8,k hi)
    const uint32_t np = (uint32_t)(((lane >> 4) << 3) | (lane & 7));
    const uint32_t kp = (uint32_t)(((lane >> 3) & 1) << 3);
    const uint32_t a1base = sb + SMEM_W1T + np * 272 + kp * 2;
    const uint32_t a2base = sb + SMEM_W2T + np * 528 + kp * 2;

    // ---- load h into fp32 C-fragment layout: [16 m rows][128 cols], 16 n8-tiles ----
    // hc[nt*4+{0,1,2,3}] = (m=g, n=tg*2), (m=g, n=tg*2+1), (m=g+8, ...), (m=g+8, +1) of tile nt
    float hc[64];
    {
        const float* r0 = inp + (size_t)(blockIdx.x * TILE_M + wid * 16 + g) * DIM;
        const float* r1 = r0 + 8 * DIM;
        #pragma unroll
        for (int nt = 0; nt < 16; nt++) {
            float2 a = *(const float2*)(r0 + nt * 8 + tg * 2);
            float2 b = *(const float2*)(r1 + nt * 8 + tg * 2);
            hc[nt * 4 + 0] = a.x; hc[nt * 4 + 1] = a.y;
            hc[nt * 4 + 2] = b.x; hc[nt * 4 + 3] = b.y;
        }
    }

    const float* b1s = (const float*)(smem + SMEM_B1S);
    const float* b2s = (const float*)(smem + SMEM_B2S);
    const float* dts = (const float*)(smem + SMEM_DTS);

    for (int step = 0; step < NSTEPS; step++) {
        const float dt = dts[step];

        // d2 accumulators [16 m][128 n], init with b2 (bias folded into accumulator)
        float d2[64];
        #pragma unroll
        for (int nt = 0; nt < 16; nt++) {
            float2 bb = *(const float2*)(b2s + nt * 8 + tg * 2);
            d2[nt * 4 + 0] = bb.x; d2[nt * 4 + 1] = bb.y;
            d2[nt * 4 + 2] = bb.x; d2[nt * 4 + 3] = bb.y;
        }

        #pragma unroll 1
        for (int nc = 0; nc < 4; nc++) {     // 64-wide N-chunk of GEMM1 == 64-wide K-chunk of GEMM2
            // ---- GEMM1 chunk: d1[16 x 64] = h @ W1[:, nc*64:+64], init with b1 ----
            float d1[32];
            #pragma unroll
            for (int nt = 0; nt < 8; nt++) {
                float2 bb = *(const float2*)(b1s + nc * 64 + nt * 8 + tg * 2);
                d1[nt * 4 + 0] = bb.x; d1[nt * 4 + 1] = bb.y;
                d1[nt * 4 + 2] = bb.x; d1[nt * 4 + 3] = bb.y;
            }
            #pragma unroll
            for (int kb = 0; kb < 8; kb++) {
                // h C-frags of tiles 2kb,2kb+1 -> A-frag of k16 block kb (register-only)
                uint32_t A0 = pack2(hc[8 * kb + 0], hc[8 * kb + 1]);
                uint32_t A1 = pack2(hc[8 * kb + 2], hc[8 * kb + 3]);
                uint32_t A2 = pack2(hc[8 * kb + 4], hc[8 * kb + 5]);
                uint32_t A3 = pack2(hc[8 * kb + 6], hc[8 * kb + 7]);
                #pragma unroll
                for (int p = 0; p < 4; p++) {
                    uint32_t B0, B1r, B2r, B3;
                    uint32_t addr = a1base + (uint32_t)(nc * 64 + p * 16) * 272 + (uint32_t)kb * 32;
                    ldsm4(B0, B1r, B2r, B3, addr);
                    mma16816(&d1[(2 * p) * 4],     A0, A1, A2, A3, B0, B1r);
                    mma16816(&d1[(2 * p + 1) * 4], A0, A1, A2, A3, B2r, B3);
                }
            }

            // ---- act = tanh(d1) -> A-frags for GEMM2 K-blocks nc*4..nc*4+3 ----
            uint32_t aF[16];
            #pragma unroll
            for (int kt = 0; kt < 4; kt++) {
                float v0 = tanh_approx(d1[8 * kt + 0]), v1 = tanh_approx(d1[8 * kt + 1]);
                float v2 = tanh_approx(d1[8 * kt + 2]), v3 = tanh_approx(d1[8 * kt + 3]);
                float v4 = tanh_approx(d1[8 * kt + 4]), v5 = tanh_approx(d1[8 * kt + 5]);
                float v6 = tanh_approx(d1[8 * kt + 6]), v7 = tanh_approx(d1[8 * kt + 7]);
                aF[kt * 4 + 0] = pack2(v0, v1);
                aF[kt * 4 + 1] = pack2(v2, v3);
                aF[kt * 4 + 2] = pack2(v4, v5);
                aF[kt * 4 + 3] = pack2(v6, v7);
            }

            // ---- GEMM2 partial: d2 += act_chunk @ W2[nc*64:+64, :] ----
            #pragma unroll
            for (int kt = 0; kt < 4; kt++) {
                const int kg = nc * 4 + kt;
                #pragma unroll
                for (int p = 0; p < 8; p++) {
                    uint32_t B0, B1r, B2r, B3;
                    uint32_t addr = a2base + (uint32_t)(p * 16) * 528 + (uint32_t)kg * 32;
                    ldsm4(B0, B1r, B2r, B3, addr);
                    mma16816(&d2[(2 * p) * 4],     aF[kt*4+0], aF[kt*4+1], aF[kt*4+2], aF[kt*4+3], B0, B1r);
                    mma16816(&d2[(2 * p + 1) * 4], aF[kt*4+0], aF[kt*4+1], aF[kt*4+2], aF[kt*4+3], B2r, B3);
                }
            }
        }

        // ---- Euler update: h += dt * (d2)   (b2 already inside d2) ----
        #pragma unroll
        for (int i = 0; i < 64; i++) hc[i] = fmaf(dt, d2[i], hc[i]);
    }

    // ---- store final h ----
    {
        float* r0 = out + (size_t)(blockIdx.x * TILE_M + wid * 16 + g) * DIM;
        float* r1 = r0 + 8 * DIM;
        #pragma unroll
        for (int nt = 0; nt < 16; nt++) {
            *(float2*)(r0 + nt * 8 + tg * 2) = make_float2(hc[nt * 4 + 0], hc[nt * 4 + 1]);
            *(float2*)(r1 + nt * 8 + tg * 2) = make_float2(hc[nt * 4 + 2], hc[nt * 4 + 3]);
        }
    }
}

extern "C" void kernel_launch(void* const* d_in, const int* in_sizes, int n_in,
                              void* d_out, int out_size) {
    const float* inp = (const float*)d_in[0];
    const float* ts  = (const float*)d_in[1];
    const float* W1  = (const float*)d_in[2];
    const float* b1  = (const float*)d_in[3];
    const float* W2  = (const float*)d_in[4];
    const float* b2  = (const float*)d_in[5];
    float* out = (float*)d_out;

    cudaFuncSetAttribute(ode_kernel, cudaFuncAttributeMaxDynamicSharedMemorySize, SMEM_BYTES);
    ode_kernel<<<NTILES, 256, SMEM_BYTES>>>(inp, ts, W1, b1, W2, b2, out);
}

// round 5
// speedup vs baseline: 1.0130x; 1.0130x over previous
#include <cuda_runtime.h>
#include <cuda_fp16.h>
#include <cstdint>

#define BATCH  32768
#define DIM    128
#define HID    256
#define NSTEPS 50
#define TILE_M 128
#define NTILES (BATCH / TILE_M)   // 256

// ---------------- SMEM layout (bytes) ----------------
// dts[64] f32 | b1[256] f32 | b2[128] f32 | W1^T f16 [256][136] | W2^T f16 [128][264]
#define SMEM_DTS   0
#define SMEM_B1S   256
#define SMEM_B2S   1280
#define SMEM_W1T   2048
#define W1T_STRIDE 136                      // f16 elems/row = 272 B (17*16B, conflict-free, 16B aligned)
#define SMEM_W2T   (SMEM_W1T + 256 * 272)   // 71680
#define W2T_STRIDE 264                      // 528 B (33*16B)
#define SMEM_BYTES (SMEM_W2T + 128 * 528)   // 139264

__device__ __forceinline__ uint32_t smem_u32(const void* p) {
    uint32_t a;
    asm("{ .reg .u64 t; cvta.to.shared.u64 t, %1; cvt.u32.u64 %0, t; }" : "=r"(a) : "l"(p));
    return a;
}

// pack two f32 -> f16x2 (lo = first arg)
__device__ __forceinline__ uint32_t pack2(float lo, float hi) {
    uint32_t r;
    asm("cvt.rn.f16x2.f32 %0, %1, %2;" : "=r"(r) : "f"(hi), "f"(lo));
    return r;
}

__device__ __forceinline__ void ldsm4(uint32_t& r0, uint32_t& r1, uint32_t& r2, uint32_t& r3, uint32_t addr) {
    asm volatile("ldmatrix.sync.aligned.m8n8.x4.shared.b16 {%0,%1,%2,%3}, [%4];"
        : "=r"(r0), "=r"(r1), "=r"(r2), "=r"(r3) : "r"(addr));
}

__device__ __forceinline__ void mma16816(float* c, uint32_t a0, uint32_t a1, uint32_t a2, uint32_t a3,
                                         uint32_t b0, uint32_t b1) {
    asm volatile("mma.sync.aligned.m16n8k16.row.col.f32.f16.f16.f32 "
        "{%0,%1,%2,%3},{%4,%5,%6,%7},{%8,%9},{%0,%1,%2,%3};"
        : "+f"(c[0]), "+f"(c[1]), "+f"(c[2]), "+f"(c[3])
        : "r"(a0), "r"(a1), "r"(a2), "r"(a3), "r"(b0), "r"(b1));
}

__device__ __forceinline__ float tanh_approx(float x) {
    float y;
    asm("tanh.approx.f32 %0, %1;" : "=f"(y) : "f"(x));
    return y;
}

__global__ void __launch_bounds__(256, 1) ode_kernel(
    const float* __restrict__ inp, const float* __restrict__ ts,
    const float* __restrict__ W1, const float* __restrict__ b1,
    const float* __restrict__ W2, const float* __restrict__ b2,
    float* __restrict__ out)
{
    extern __shared__ char smem[];
    const uint32_t sb = smem_u32(smem);
    const int tid  = threadIdx.x;
    const int lane = tid & 31;
    const int wid  = tid >> 5;          // 8 warps, each owns 16 rows
    const int g    = lane >> 2;         // group id 0..7
    const int tg   = lane & 3;          // thread-in-group

    // ---- stage constants ----
    if (tid < NSTEPS) ((float*)(smem + SMEM_DTS))[tid] = ts[tid + 1] - ts[tid];
    for (int i = tid; i < HID; i += 256) ((float*)(smem + SMEM_B1S))[i] = b1[i];
    for (int i = tid; i < DIM; i += 256) ((float*)(smem + SMEM_B2S))[i] = b2[i];

    // ---- weights -> SMEM f16, transposed, padded strides ----
    __half* W1t = (__half*)(smem + SMEM_W1T);   // [n=256][k padded 136]
    __half* W2t = (__half*)(smem + SMEM_W2T);   // [n=128][k padded 264]
    for (int idx = tid; idx < DIM * HID; idx += 256) {      // W1: [128 k][256 n] row-major
        int n = idx & 255, k = idx >> 8;                    // gmem-coalesced over n
        W1t[n * W1T_STRIDE + k] = __float2half_rn(W1[k * HID + n]);
    }
    for (int idx = tid; idx < DIM * HID; idx += 256) {      // W2: [256 k][128 n]
        int n = idx & 127, k = idx >> 7;
        W2t[n * W2T_STRIDE + k] = __float2half_rn(W2[k * DIM + n]);
    }
    __syncthreads();

    // ---- ldmatrix per-lane address components ----
    const uint32_t np = (uint32_t)(((lane >> 4) << 3) | (lane & 7));
    const uint32_t kp = (uint32_t)(((lane >> 3) & 1) << 3);
    const uint32_t a1base = sb + SMEM_W1T + np * 272 + kp * 2;
    const uint32_t a2base = sb + SMEM_W2T + np * 528 + kp * 2;

    // ---- load h into fp32 C-fragment layout: [16 m rows][128 cols], 16 n8-tiles ----
    float hc[64];
    {
        const float* r0 = inp + (size_t)(blockIdx.x * TILE_M + wid * 16 + g) * DIM;
        const float* r1 = r0 + 8 * DIM;
        #pragma unroll
        for (int nt = 0; nt < 16; nt++) {
            float2 a = *(const float2*)(r0 + nt * 8 + tg * 2);
            float2 b = *(const float2*)(r1 + nt * 8 + tg * 2);
            hc[nt * 4 + 0] = a.x; hc[nt * 4 + 1] = a.y;
            hc[nt * 4 + 2] = b.x; hc[nt * 4 + 3] = b.y;
        }
    }

    const float* b1s = (const float*)(smem + SMEM_B1S);
    const float* b2s = (const float*)(smem + SMEM_B2S);
    const float* dts = (const float*)(smem + SMEM_DTS);

    for (int step = 0; step < NSTEPS; step++) {
        const float dt = dts[step];

        // ---- pack A-frags of h ONCE per step (reused by all 4 N-chunks of GEMM1) ----
        // aH[4*kb+i] = f16x2 of (hc[8kb+2i], hc[8kb+2i+1])
        uint32_t aH[32];
        #pragma unroll
        for (int kb = 0; kb < 8; kb++) {
            aH[4*kb+0] = pack2(hc[8*kb+0], hc[8*kb+1]);
            aH[4*kb+1] = pack2(hc[8*kb+2], hc[8*kb+3]);
            aH[4*kb+2] = pack2(hc[8*kb+4], hc[8*kb+5]);
            aH[4*kb+3] = pack2(hc[8*kb+6], hc[8*kb+7]);
        }

        // ---- fold bias: hc += dt*b2; GEMM2 then accumulates dt*act@W2 directly into hc ----
        #pragma unroll
        for (int nt = 0; nt < 16; nt++) {
            float2 bb = *(const float2*)(b2s + nt * 8 + tg * 2);
            hc[nt * 4 + 0] = fmaf(dt, bb.x, hc[nt * 4 + 0]);
            hc[nt * 4 + 1] = fmaf(dt, bb.y, hc[nt * 4 + 1]);
            hc[nt * 4 + 2] = fmaf(dt, bb.x, hc[nt * 4 + 2]);
            hc[nt * 4 + 3] = fmaf(dt, bb.y, hc[nt * 4 + 3]);
        }

        #pragma unroll
        for (int nc = 0; nc < 4; nc++) {     // 64-wide N-chunk of GEMM1 == 64-wide K-chunk of GEMM2
            // ---- GEMM1 chunk: d1[16 x 64] = h @ W1[:, nc*64:+64], init with b1 ----
            float d1[32];
            #pragma unroll
            for (int nt = 0; nt < 8; nt++) {
                float2 bb = *(const float2*)(b1s + nc * 64 + nt * 8 + tg * 2);
                d1[nt * 4 + 0] = bb.x; d1[nt * 4 + 1] = bb.y;
                d1[nt * 4 + 2] = bb.x; d1[nt * 4 + 3] = bb.y;
            }
            #pragma unroll
            for (int kb = 0; kb < 8; kb++) {
                #pragma unroll
                for (int p = 0; p < 4; p++) {
                    uint32_t B0, B1r, B2r, B3;
                    uint32_t addr = a1base + (uint32_t)(nc * 64 + p * 16) * 272 + (uint32_t)kb * 32;
                    ldsm4(B0, B1r, B2r, B3, addr);
                    mma16816(&d1[(2 * p) * 4],     aH[4*kb+0], aH[4*kb+1], aH[4*kb+2], aH[4*kb+3], B0, B1r);
                    mma16816(&d1[(2 * p + 1) * 4], aH[4*kb+0], aH[4*kb+1], aH[4*kb+2], aH[4*kb+3], B2r, B3);
                }
            }

            // ---- act = dt * tanh(d1) -> f16 A-frags for GEMM2 K-blocks nc*4..nc*4+3 ----
            uint32_t aF[16];
            #pragma unroll
            for (int kt = 0; kt < 4; kt++) {
                float v0 = tanh_approx(d1[8 * kt + 0]), v1 = tanh_approx(d1[8 * kt + 1]);
                float v2 = tanh_approx(d1[8 * kt + 2]), v3 = tanh_approx(d1[8 * kt + 3]);
                float v4 = tanh_approx(d1[8 * kt + 4]), v5 = tanh_approx(d1[8 * kt + 5]);
                float v6 = tanh_approx(d1[8 * kt + 6]), v7 = tanh_approx(d1[8 * kt + 7]);
                aF[kt * 4 + 0] = pack2(dt * v0, dt * v1);
                aF[kt * 4 + 1] = pack2(dt * v2, dt * v3);
                aF[kt * 4 + 2] = pack2(dt * v4, dt * v5);
                aF[kt * 4 + 3] = pack2(dt * v6, dt * v7);
            }

            // ---- GEMM2 partial: hc += (dt*act_chunk) @ W2[nc*64:+64, :] ----
            #pragma unroll
            for (int kt = 0; kt < 4; kt++) {
                const int kg = nc * 4 + kt;
                #pragma unroll
                for (int p = 0; p < 8; p++) {
                    uint32_t B0, B1r, B2r, B3;
                    uint32_t addr = a2base + (uint32_t)(p * 16) * 528 + (uint32_t)kg * 32;
                    ldsm4(B0, B1r, B2r, B3, addr);
                    mma16816(&hc[(2 * p) * 4],     aF[kt*4+0], aF[kt*4+1], aF[kt*4+2], aF[kt*4+3], B0, B1r);
                    mma16816(&hc[(2 * p + 1) * 4], aF[kt*4+0], aF[kt*4+1], aF[kt*4+2], aF[kt*4+3], B2r, B3);
                }
            }
        }
        // hc now holds h_{step+1}; aH is dead until repacked next step.
    }

    // ---- store final h ----
    {
        float* r0 = out + (size_t)(blockIdx.x * TILE_M + wid * 16 + g) * DIM;
        float* r1 = r0 + 8 * DIM;
        #pragma unroll
        for (int nt = 0; nt < 16; nt++) {
            *(float2*)(r0 + nt * 8 + tg * 2) = make_float2(hc[nt * 4 + 0], hc[nt * 4 + 1]);
            *(float2*)(r1 + nt * 8 + tg * 2) = make_float2(hc[nt * 4 + 2], hc[nt * 4 + 3]);
        }
    }
}

extern "C" void kernel_launch(void* const* d_in, const int* in_sizes, int n_in,
                              void* d_out, int out_size) {
    const float* inp = (const float*)d_in[0];
    const float* ts  = (const float*)d_in[1];
    const float* W1  = (const float*)d_in[2];
    const float* b1  = (const float*)d_in[3];
    const float* W2  = (const float*)d_in[4];
    const float* b2  = (const float*)d_in[5];
    float* out = (float*)d_out;

    cudaFuncSetAttribute(ode_kernel, cudaFuncAttributeMaxDynamicSharedMemorySize, SMEM_BYTES);
    ode_kernel<<<NTILES, 256, SMEM_BYTES>>>(inp, ts, W1, b1, W2, b2, out);
}